// round 14
// baseline (speedup 1.0000x reference)
#include <cuda_runtime.h>
#include <cuda_bf16.h>
#include <cstdint>

// GraphSAGE layer: out = relu(concat(x, mean_neigh(x)) @ W + b)
// N=100000 nodes, d=64, E=1250000 edges, W [128,64], b [64], out [N,64] fp32.
//
// 3 launches: k_build (count -> scan -> fill, grid barriers, 256 co-resident
// blocks = 262K threads), k_aggr (segment gather, 8 LDGs in flight), k_out.

#define N_NODES 100000
#define N_EDGES 1250000
#define DIM     64
#define DIM4    16              // DIM / 4 (float4 words per row)
#define NPB     128             // nodes per block in the GEMM kernel
#define XA_PAD  132             // padded row stride (floats) for x_aggr tile
#define NB      256             // k_build blocks; 2/SM at <=32 regs -> co-resident

// Scratch (static __device__, zero-initialized at load; no cudaMalloc allowed)
__device__ float4 g_neigh4[N_NODES * DIM4];   // mean-aggregated neighbor feats
__device__ int    g_deg[N_NODES];             // zeroed at end of each replay
__device__ int    g_off[N_NODES];             // GLOBAL exclusive prefix
__device__ int    g_cur[N_NODES];             // fill cursors
__device__ int    g_src[N_EDGES];
__device__ int    g_bsum[NB];
__device__ unsigned g_arr[3];                 // monotonic grid-barrier counters

#define FMA2(d, a, b, c) \
    asm("fma.rn.f32x2 %0, %1, %2, %3;" : "=l"(d) : "l"(a), "l"(b), "l"(c))

#define PACK2(d, f) \
    asm("mov.b64 %0, {%1, %1};" : "=l"(d) : "r"(__float_as_uint(f)))

// dtype probe: first 4 values as int64 all in [0,N) <=> true int64 data.
__device__ __forceinline__ bool detect_is64(const long long* ei) {
    bool ok = true;
    #pragma unroll
    for (int k = 0; k < 4; k++) {
        long long v = ei[k];
        if (v < 0 || v >= (long long)N_NODES) ok = false;
    }
    return ok;
}

// Device-wide barrier over NB co-resident blocks; monotonic counter so state
// is replay-clean without resets.
__device__ __forceinline__ void grid_barrier(unsigned* ctr) {
    __shared__ unsigned s_old;
    __syncthreads();
    if (threadIdx.x == 0) {
        __threadfence();
        s_old = atomicAdd(ctr, 1u);
        unsigned base = (s_old / NB) * NB;
        while ((unsigned)(atomicAdd(ctr, 0u) - base) < NB) { }
        __threadfence();
    }
    __syncthreads();
}

// ---------------------------------------------------------------------------
// Kernel 1: count -> scan -> fill in ONE launch (256 blocks x 1024 threads)
// ---------------------------------------------------------------------------
__global__ void __launch_bounds__(1024, 2) k_build(const long long* __restrict__ ei) {
    const bool is64 = detect_is64(ei);
    const int  NT   = NB * 1024;                 // 262144 threads
    const int  NPAIR = N_EDGES / 2;              // 625000
    int gt = blockIdx.x * 1024 + threadIdx.x;

    // ---- Phase 1: degree histogram (RED, no return; 2 edges/iteration) ----
    for (int i = gt; i < NPAIR; i += NT) {
        int c0, c1;
        if (is64) {
            longlong2 cp = ((const longlong2*)(ei + N_EDGES))[i];
            c0 = (int)cp.x; c1 = (int)cp.y;
        } else {
            int2 cp = ((const int2*)((const int*)ei + N_EDGES))[i];
            c0 = cp.x; c1 = cp.y;
        }
        atomicAdd(&g_deg[c0], 1);
        atomicAdd(&g_deg[c1], 1);
    }
    grid_barrier(&g_arr[0]);

    // ---- Phase 2: exclusive scan of g_deg -> g_off / g_cur ----
    __shared__ int wsum[32];
    __shared__ int s_base;
    int i = gt;                                   // node index (only i < N active)
    int v = (i < N_NODES) ? g_deg[i] : 0;
    int lane = threadIdx.x & 31, w = threadIdx.x >> 5;

    int s = v;
    #pragma unroll
    for (int o = 1; o < 32; o <<= 1) {
        int t = __shfl_up_sync(~0u, s, o);
        if (lane >= o) s += t;
    }
    if (lane == 31) wsum[w] = s;
    __syncthreads();
    if (w == 0) {
        int t = wsum[lane];
        #pragma unroll
        for (int o = 1; o < 32; o <<= 1) {
            int u = __shfl_up_sync(~0u, t, o);
            if (lane >= o) t += u;
        }
        wsum[lane] = t;
    }
    __syncthreads();
    int base_w = w ? wsum[w - 1] : 0;
    int excl   = base_w + s - v;                  // block-local exclusive prefix

    if (threadIdx.x == 1023) g_bsum[blockIdx.x] = base_w + s;
    grid_barrier(&g_arr[1]);                      // publishes bsum (fenced)

    // base = sum of g_bsum[0..bid)
    if (w == 0) {
        int partial = 0;
        #pragma unroll
        for (int k = 0; k < NB / 32; k++) {
            int idx = lane + 32 * k;
            if (idx < blockIdx.x) partial += g_bsum[idx];
        }
        #pragma unroll
        for (int o = 16; o > 0; o >>= 1)
            partial += __shfl_down_sync(~0u, partial, o);
        if (lane == 0) s_base = partial;
    }
    __syncthreads();
    if (i < N_NODES) {
        int o = s_base + excl;
        g_off[i] = o;
        g_cur[i] = o;
    }
    grid_barrier(&g_arr[2]);                      // cursors visible everywhere

    // ---- Phase 3: scatter source indices. 2 pairs (4 edges) per iteration:
    //      4 atomic returns in flight per thread to hide ATOMG latency. ----
    for (int q = gt; q < NPAIR; q += 2 * NT) {
        int q2 = q + NT;
        bool have2 = (q2 < NPAIR);
        int r0, r1, c0, c1, r2, r3, c2, c3;
        if (is64) {
            longlong2 rp = ((const longlong2*)ei)[q];
            longlong2 cp = ((const longlong2*)(ei + N_EDGES))[q];
            r0 = (int)rp.x; r1 = (int)rp.y;
            c0 = (int)cp.x; c1 = (int)cp.y;
            if (have2) {
                longlong2 rq = ((const longlong2*)ei)[q2];
                longlong2 cq = ((const longlong2*)(ei + N_EDGES))[q2];
                r2 = (int)rq.x; r3 = (int)rq.y;
                c2 = (int)cq.x; c3 = (int)cq.y;
            }
        } else {
            const int* e = (const int*)ei;
            int2 rp = ((const int2*)e)[q];
            int2 cp = ((const int2*)(e + N_EDGES))[q];
            r0 = rp.x; r1 = rp.y; c0 = cp.x; c1 = cp.y;
            if (have2) {
                int2 rq = ((const int2*)e)[q2];
                int2 cq = ((const int2*)(e + N_EDGES))[q2];
                r2 = rq.x; r3 = rq.y; c2 = cq.x; c3 = cq.y;
            }
        }
        int s0 = atomicAdd(&g_cur[c0], 1);
        int s1 = atomicAdd(&g_cur[c1], 1);
        int s2 = 0, s3 = 0;
        if (have2) {
            s2 = atomicAdd(&g_cur[c2], 1);
            s3 = atomicAdd(&g_cur[c3], 1);
        }
        g_src[s0] = r0;
        g_src[s1] = r1;
        if (have2) {
            g_src[s2] = r2;
            g_src[s3] = r3;
        }
    }
}

// ---------------------------------------------------------------------------
// Kernel 2: segment-sum gather. One warp per destination node.
//   16 lanes x float4 cover the row; 2 edge streams (h) merged via shfl_xor(16).
//   Main loop keeps 4 src + 4 feature-row loads in flight per lane.
//   Tail: re-zero g_deg[d] so the next graph replay starts clean.
// ---------------------------------------------------------------------------
__global__ void __launch_bounds__(256) k_aggr(const float4* __restrict__ x4) {
    int tid  = threadIdx.x;
    int lane = tid & 31;
    int d    = blockIdx.x * 8 + (tid >> 5);
    if (d >= N_NODES) return;
    int p = lane & 15;
    int h = lane >> 4;

    int off = g_off[d];
    int deg = g_deg[d];
    int m   = (deg + 1 - h) >> 1;        // elements in this stream (stride 2)
    int j   = off + h;
    float4 acc = make_float4(0.f, 0.f, 0.f, 0.f);

    while (m >= 4) {                     // 8 independent LDGs in flight
        int a0 = g_src[j];
        int a1 = g_src[j + 2];
        int a2 = g_src[j + 4];
        int a3 = g_src[j + 6];
        float4 v0 = x4[a0 * DIM4 + p];
        float4 v1 = x4[a1 * DIM4 + p];
        float4 v2 = x4[a2 * DIM4 + p];
        float4 v3 = x4[a3 * DIM4 + p];
        acc.x += (v0.x + v1.x) + (v2.x + v3.x);
        acc.y += (v0.y + v1.y) + (v2.y + v3.y);
        acc.z += (v0.z + v1.z) + (v2.z + v3.z);
        acc.w += (v0.w + v1.w) + (v2.w + v3.w);
        j += 8; m -= 4;
    }
    while (m > 0) {
        int a = g_src[j];
        float4 v = x4[a * DIM4 + p];
        acc.x += v.x; acc.y += v.y; acc.z += v.z; acc.w += v.w;
        j += 2; m--;
    }

    acc.x += __shfl_xor_sync(~0u, acc.x, 16);
    acc.y += __shfl_xor_sync(~0u, acc.y, 16);
    acc.z += __shfl_xor_sync(~0u, acc.z, 16);
    acc.w += __shfl_xor_sync(~0u, acc.w, 16);

    if (h == 0) {
        float inv = (deg > 0) ? (1.0f / (float)deg) : 0.f;
        acc.x *= inv; acc.y *= inv; acc.z *= inv; acc.w *= inv;
        g_neigh4[d * DIM4 + p] = acc;
        if (p == 0) g_deg[d] = 0;        // leave clean state for next replay
    }
}

// ---------------------------------------------------------------------------
// Kernel 3: fused GEMM + bias + relu.
//   Block = 256 threads, 128 nodes. 4 nodes/thread x 8 outputs (f32x2 packed).
// ---------------------------------------------------------------------------
#define SMEM_OUT (128 * 64 * 4 + NPB * XA_PAD * 4)

__global__ void __launch_bounds__(256) k_out(const float4* __restrict__ x4,
                                             const float*  __restrict__ W,
                                             const float*  __restrict__ b,
                                             float*        __restrict__ out) {
    extern __shared__ float sm[];
    float* sW = sm;                      // [128][64]
    float* sX = sm + 128 * 64;           // [NPB][XA_PAD]
    int tid   = threadIdx.x;
    int nbase = blockIdx.x * NPB;

    for (int i = tid; i < 128 * 64 / 4; i += 256)
        ((float4*)sW)[i] = ((const float4*)W)[i];

    for (int i = tid; i < NPB * 2 * DIM4; i += 256) {
        int node_l = i >> 5;             // 0..127
        int f4     = i & 31;             // 0..15 -> x, 16..31 -> neigh (pre-meaned)
        int node   = nbase + node_l;
        float4 v   = make_float4(0.f, 0.f, 0.f, 0.f);
        if (node < N_NODES) {
            v = (f4 < DIM4) ? x4[node * DIM4 + f4]
                            : g_neigh4[node * DIM4 + (f4 - DIM4)];
        }
        *(float4*)(sX + node_l * XA_PAD + f4 * 4) = v;
    }
    __syncthreads();

    int ng = tid >> 3;                   // 0..31 -> 4 nodes each
    int jg = (tid & 7) * 8;              // output column group
    const float* xa0 = sX + (ng * 4 + 0) * XA_PAD;
    const float* xa1 = sX + (ng * 4 + 1) * XA_PAD;
    const float* xa2 = sX + (ng * 4 + 2) * XA_PAD;
    const float* xa3 = sX + (ng * 4 + 3) * XA_PAD;

    unsigned long long acc[4][4];
    #pragma unroll
    for (int n = 0; n < 4; n++)
        #pragma unroll
        for (int j = 0; j < 4; j++) acc[n][j] = 0ULL;

    #pragma unroll 2
    for (int k = 0; k < 128; k += 4) {
        float4 a0 = *(const float4*)(xa0 + k);
        float4 a1 = *(const float4*)(xa1 + k);
        float4 a2 = *(const float4*)(xa2 + k);
        float4 a3 = *(const float4*)(xa3 + k);
        #pragma unroll
        for (int kk = 0; kk < 4; kk++) {
            const ulonglong2* wr = (const ulonglong2*)(sW + (k + kk) * 64 + jg);
            ulonglong2 w01 = wr[0];      // W[k][jg+0..3] as two f32x2
            ulonglong2 w23 = wr[1];      // W[k][jg+4..7]
            unsigned long long p0, p1, p2, p3;
            PACK2(p0, (&a0.x)[kk]);
            PACK2(p1, (&a1.x)[kk]);
            PACK2(p2, (&a2.x)[kk]);
            PACK2(p3, (&a3.x)[kk]);
            FMA2(acc[0][0], p0, w01.x, acc[0][0]);
            FMA2(acc[0][1], p0, w01.y, acc[0][1]);
            FMA2(acc[0][2], p0, w23.x, acc[0][2]);
            FMA2(acc[0][3], p0, w23.y, acc[0][3]);
            FMA2(acc[1][0], p1, w01.x, acc[1][0]);
            FMA2(acc[1][1], p1, w01.y, acc[1][1]);
            FMA2(acc[1][2], p1, w23.x, acc[1][2]);
            FMA2(acc[1][3], p1, w23.y, acc[1][3]);
            FMA2(acc[2][0], p2, w01.x, acc[2][0]);
            FMA2(acc[2][1], p2, w01.y, acc[2][1]);
            FMA2(acc[2][2], p2, w23.x, acc[2][2]);
            FMA2(acc[2][3], p2, w23.y, acc[2][3]);
            FMA2(acc[3][0], p3, w01.x, acc[3][0]);
            FMA2(acc[3][1], p3, w01.y, acc[3][1]);
            FMA2(acc[3][2], p3, w23.x, acc[3][2]);
            FMA2(acc[3][3], p3, w23.y, acc[3][3]);
        }
    }

    float bias[8];
    #pragma unroll
    for (int j = 0; j < 8; j++) bias[j] = b[jg + j];

    #pragma unroll
    for (int n = 0; n < 4; n++) {
        int node = nbase + ng * 4 + n;
        if (node >= N_NODES) break;
        float o[8];
        #pragma unroll
        for (int j = 0; j < 4; j++) {
            unsigned int lo, hi;
            asm("mov.b64 {%0, %1}, %2;" : "=r"(lo), "=r"(hi) : "l"(acc[n][j]));
            o[2*j]   = __uint_as_float(lo);
            o[2*j+1] = __uint_as_float(hi);
        }
        #pragma unroll
        for (int j = 0; j < 8; j++) o[j] = fmaxf(o[j] + bias[j], 0.f);
        *(float4*)(out + node * DIM + jg)     = make_float4(o[0], o[1], o[2], o[3]);
        *(float4*)(out + node * DIM + jg + 4) = make_float4(o[4], o[5], o[6], o[7]);
    }
}

// ---------------------------------------------------------------------------
extern "C" void kernel_launch(void* const* d_in, const int* in_sizes, int n_in,
                              void* d_out, int out_size) {
    const float*     x  = (const float*)d_in[0];
    const long long* ei = (const long long*)d_in[1];
    const float*     W  = (const float*)d_in[2];
    const float*     b  = (const float*)d_in[3];
    float*           out = (float*)d_out;

    k_build<<<NB, 1024>>>(ei);
    k_aggr<<<(N_NODES + 7) / 8, 256>>>((const float4*)x);

    int grid = (N_NODES + NPB - 1) / NPB;   // 782
    cudaFuncSetAttribute(k_out, cudaFuncAttributeMaxDynamicSharedMemorySize, SMEM_OUT);
    k_out<<<grid, 256, SMEM_OUT>>>((const float4*)x, W, b, out);
}

// round 15
// speedup vs baseline: 1.0257x; 1.0257x over previous
#include <cuda_runtime.h>
#include <cuda_bf16.h>
#include <cstdint>

// GraphSAGE layer: out = relu(concat(x, mean_neigh(x)) @ W + b)
// N=100000 nodes, d=64, E=1250000 edges, W [128,64], b [64], out [N,64] fp32.
//
// 5 launches (R12-proven structure): count -> scan (single-pass, spin barrier)
// -> fill -> aggr (4-deep pipelined gather) -> gemm.
// No atomic feature math; g_deg re-zeroed by aggr tail (replay-clean state).

#define N_NODES 100000
#define N_EDGES 1250000
#define DIM     64
#define DIM4    16              // DIM / 4 (float4 words per row)
#define NPB     128             // nodes per block in the GEMM kernel
#define XA_PAD  132             // padded row stride (floats) for x_aggr tile
#define SCAN_BLK 98             // ceil(N_NODES / 1024)

// Scratch (static __device__, zero-initialized at load; no cudaMalloc allowed)
__device__ float4 g_neigh4[N_NODES * DIM4];   // mean-aggregated neighbor feats
__device__ int    g_deg[N_NODES];             // zeroed at end of each replay
__device__ int    g_off[N_NODES];             // GLOBAL exclusive prefix
__device__ int    g_cur[N_NODES];             // fill cursors (= g_off at start)
__device__ int    g_src[N_EDGES];
__device__ int    g_bsum[SCAN_BLK];
__device__ unsigned g_arrive;                 // monotonic across replays

#define FMA2(d, a, b, c) \
    asm("fma.rn.f32x2 %0, %1, %2, %3;" : "=l"(d) : "l"(a), "l"(b), "l"(c))

#define PACK2(d, f) \
    asm("mov.b64 %0, {%1, %1};" : "=l"(d) : "r"(__float_as_uint(f)))

// dtype probe: first 4 values as int64 all in [0,N) <=> true int64 data.
__device__ __forceinline__ bool detect_is64(const long long* ei) {
    bool ok = true;
    #pragma unroll
    for (int k = 0; k < 4; k++) {
        long long v = ei[k];
        if (v < 0 || v >= (long long)N_NODES) ok = false;
    }
    return ok;
}

// ---------------------------------------------------------------------------
// Kernel 1: degree histogram over destination column (2 edges per thread)
// ---------------------------------------------------------------------------
__global__ void __launch_bounds__(256) k_count(const long long* __restrict__ ei) {
    int i = blockIdx.x * blockDim.x + threadIdx.x;   // pair index
    if (i >= N_EDGES / 2) return;
    int c0, c1;
    if (detect_is64(ei)) {
        longlong2 cp = ((const longlong2*)(ei + N_EDGES))[i];
        c0 = (int)cp.x; c1 = (int)cp.y;
    } else {
        int2 cp = ((const int2*)((const int*)ei + N_EDGES))[i];
        c0 = cp.x; c1 = cp.y;
    }
    atomicAdd(&g_deg[c0], 1);
    atomicAdd(&g_deg[c1], 1);
}

// ---------------------------------------------------------------------------
// Kernel 2: single-pass exclusive scan of g_deg -> GLOBAL g_off / g_cur.
//   98 co-resident blocks; monotonic arrival counter (replay-safe).
// ---------------------------------------------------------------------------
__global__ void __launch_bounds__(1024) k_scan() {
    __shared__ int wsum[32];
    __shared__ unsigned s_old;
    __shared__ int s_base;

    int i = blockIdx.x * 1024 + threadIdx.x;
    int v = (i < N_NODES) ? g_deg[i] : 0;
    int lane = threadIdx.x & 31, w = threadIdx.x >> 5;

    int s = v;
    #pragma unroll
    for (int o = 1; o < 32; o <<= 1) {
        int t = __shfl_up_sync(~0u, s, o);
        if (lane >= o) s += t;
    }
    if (lane == 31) wsum[w] = s;
    __syncthreads();
    if (w == 0) {
        int t = wsum[lane];
        #pragma unroll
        for (int o = 1; o < 32; o <<= 1) {
            int u = __shfl_up_sync(~0u, t, o);
            if (lane >= o) t += u;
        }
        wsum[lane] = t;
    }
    __syncthreads();
    int base_w = w ? wsum[w - 1] : 0;
    int excl   = base_w + s - v;         // block-local exclusive prefix

    if (threadIdx.x == 1023) {
        g_bsum[blockIdx.x] = base_w + s;
        __threadfence();
        s_old = atomicAdd(&g_arrive, 1u);
    }
    __syncthreads();

    if (threadIdx.x == 0) {
        unsigned base = (s_old / SCAN_BLK) * SCAN_BLK;
        while ((unsigned)(atomicAdd(&g_arrive, 0u) - base) < SCAN_BLK) { }
        __threadfence();
    }
    __syncthreads();

    if (w == 0) {
        int partial = 0;
        #pragma unroll
        for (int k = 0; k < 4; k++) {
            int idx = lane + 32 * k;
            if (idx < blockIdx.x) partial += g_bsum[idx];
        }
        #pragma unroll
        for (int o = 16; o > 0; o >>= 1)
            partial += __shfl_down_sync(~0u, partial, o);
        if (lane == 0) s_base = partial;
    }
    __syncthreads();

    if (i < N_NODES) {
        int o = s_base + excl;
        g_off[i] = o;
        g_cur[i] = o;
    }
}

// ---------------------------------------------------------------------------
// Kernel 3: scatter source indices into CSR slots (1 atomic/thread, max TLP)
// ---------------------------------------------------------------------------
__global__ void __launch_bounds__(256) k_fill(const long long* __restrict__ ei) {
    int i = blockIdx.x * blockDim.x + threadIdx.x;
    if (i >= N_EDGES) return;
    int r, c;
    if (detect_is64(ei)) { r = (int)ei[i]; c = (int)ei[N_EDGES + i]; }
    else { const int* e = (const int*)ei; r = e[i]; c = e[N_EDGES + i]; }
    int slot = atomicAdd(&g_cur[c], 1);
    g_src[slot] = r;
}

// ---------------------------------------------------------------------------
// Kernel 4: segment-sum gather. One warp per destination node.
//   16 lanes x float4 cover the row; 2 edge streams (h) merged via shfl_xor(16).
//   Main loop keeps 4 src + 4 feature-row loads in flight per lane (8 LDGs).
//   Tail: re-zero g_deg[d] so the next graph replay starts clean.
// ---------------------------------------------------------------------------
__global__ void __launch_bounds__(256) k_aggr(const float4* __restrict__ x4) {
    int tid  = threadIdx.x;
    int lane = tid & 31;
    int d    = blockIdx.x * 8 + (tid >> 5);
    if (d >= N_NODES) return;
    int p = lane & 15;
    int h = lane >> 4;

    int off = g_off[d];
    int deg = g_deg[d];
    int m   = (deg + 1 - h) >> 1;        // elements in this stream (stride 2)
    int j   = off + h;
    float4 acc = make_float4(0.f, 0.f, 0.f, 0.f);

    while (m >= 4) {                     // 8 independent LDGs in flight
        int a0 = g_src[j];
        int a1 = g_src[j + 2];
        int a2 = g_src[j + 4];
        int a3 = g_src[j + 6];
        float4 v0 = x4[a0 * DIM4 + p];
        float4 v1 = x4[a1 * DIM4 + p];
        float4 v2 = x4[a2 * DIM4 + p];
        float4 v3 = x4[a3 * DIM4 + p];
        acc.x += (v0.x + v1.x) + (v2.x + v3.x);
        acc.y += (v0.y + v1.y) + (v2.y + v3.y);
        acc.z += (v0.z + v1.z) + (v2.z + v3.z);
        acc.w += (v0.w + v1.w) + (v2.w + v3.w);
        j += 8; m -= 4;
    }
    while (m > 0) {
        int a = g_src[j];
        float4 v = x4[a * DIM4 + p];
        acc.x += v.x; acc.y += v.y; acc.z += v.z; acc.w += v.w;
        j += 2; m--;
    }

    acc.x += __shfl_xor_sync(~0u, acc.x, 16);
    acc.y += __shfl_xor_sync(~0u, acc.y, 16);
    acc.z += __shfl_xor_sync(~0u, acc.z, 16);
    acc.w += __shfl_xor_sync(~0u, acc.w, 16);

    if (h == 0) {
        float inv = (deg > 0) ? (1.0f / (float)deg) : 0.f;
        acc.x *= inv; acc.y *= inv; acc.z *= inv; acc.w *= inv;
        g_neigh4[d * DIM4 + p] = acc;
        if (p == 0) g_deg[d] = 0;        // leave clean state for next replay
    }
}

// ---------------------------------------------------------------------------
// Kernel 5: fused GEMM + bias + relu.
//   Block = 256 threads, 128 nodes. 4 nodes/thread x 8 outputs (f32x2 packed).
// ---------------------------------------------------------------------------
#define SMEM_OUT (128 * 64 * 4 + NPB * XA_PAD * 4)

__global__ void __launch_bounds__(256) k_out(const float4* __restrict__ x4,
                                             const float*  __restrict__ W,
                                             const float*  __restrict__ b,
                                             float*        __restrict__ out) {
    extern __shared__ float sm[];
    float* sW = sm;                      // [128][64]
    float* sX = sm + 128 * 64;           // [NPB][XA_PAD]
    int tid   = threadIdx.x;
    int nbase = blockIdx.x * NPB;

    for (int i = tid; i < 128 * 64 / 4; i += 256)
        ((float4*)sW)[i] = ((const float4*)W)[i];

    for (int i = tid; i < NPB * 2 * DIM4; i += 256) {
        int node_l = i >> 5;             // 0..127
        int f4     = i & 31;             // 0..15 -> x, 16..31 -> neigh (pre-meaned)
        int node   = nbase + node_l;
        float4 v   = make_float4(0.f, 0.f, 0.f, 0.f);
        if (node < N_NODES) {
            v = (f4 < DIM4) ? x4[node * DIM4 + f4]
                            : g_neigh4[node * DIM4 + (f4 - DIM4)];
        }
        *(float4*)(sX + node_l * XA_PAD + f4 * 4) = v;
    }
    __syncthreads();

    int ng = tid >> 3;                   // 0..31 -> 4 nodes each
    int jg = (tid & 7) * 8;              // output column group
    const float* xa0 = sX + (ng * 4 + 0) * XA_PAD;
    const float* xa1 = sX + (ng * 4 + 1) * XA_PAD;
    const float* xa2 = sX + (ng * 4 + 2) * XA_PAD;
    const float* xa3 = sX + (ng * 4 + 3) * XA_PAD;

    unsigned long long acc[4][4];
    #pragma unroll
    for (int n = 0; n < 4; n++)
        #pragma unroll
        for (int j = 0; j < 4; j++) acc[n][j] = 0ULL;

    #pragma unroll 2
    for (int k = 0; k < 128; k += 4) {
        float4 a0 = *(const float4*)(xa0 + k);
        float4 a1 = *(const float4*)(xa1 + k);
        float4 a2 = *(const float4*)(xa2 + k);
        float4 a3 = *(const float4*)(xa3 + k);
        #pragma unroll
        for (int kk = 0; kk < 4; kk++) {
            const ulonglong2* wr = (const ulonglong2*)(sW + (k + kk) * 64 + jg);
            ulonglong2 w01 = wr[0];      // W[k][jg+0..3] as two f32x2
            ulonglong2 w23 = wr[1];      // W[k][jg+4..7]
            unsigned long long p0, p1, p2, p3;
            PACK2(p0, (&a0.x)[kk]);
            PACK2(p1, (&a1.x)[kk]);
            PACK2(p2, (&a2.x)[kk]);
            PACK2(p3, (&a3.x)[kk]);
            FMA2(acc[0][0], p0, w01.x, acc[0][0]);
            FMA2(acc[0][1], p0, w01.y, acc[0][1]);
            FMA2(acc[0][2], p0, w23.x, acc[0][2]);
            FMA2(acc[0][3], p0, w23.y, acc[0][3]);
            FMA2(acc[1][0], p1, w01.x, acc[1][0]);
            FMA2(acc[1][1], p1, w01.y, acc[1][1]);
            FMA2(acc[1][2], p1, w23.x, acc[1][2]);
            FMA2(acc[1][3], p1, w23.y, acc[1][3]);
            FMA2(acc[2][0], p2, w01.x, acc[2][0]);
            FMA2(acc[2][1], p2, w01.y, acc[2][1]);
            FMA2(acc[2][2], p2, w23.x, acc[2][2]);
            FMA2(acc[2][3], p2, w23.y, acc[2][3]);
            FMA2(acc[3][0], p3, w01.x, acc[3][0]);
            FMA2(acc[3][1], p3, w01.y, acc[3][1]);
            FMA2(acc[3][2], p3, w23.x, acc[3][2]);
            FMA2(acc[3][3], p3, w23.y, acc[3][3]);
        }
    }

    float bias[8];
    #pragma unroll
    for (int j = 0; j < 8; j++) bias[j] = b[jg + j];

    #pragma unroll
    for (int n = 0; n < 4; n++) {
        int node = nbase + ng * 4 + n;
        if (node >= N_NODES) break;
        float o[8];
        #pragma unroll
        for (int j = 0; j < 4; j++) {
            unsigned int lo, hi;
            asm("mov.b64 {%0, %1}, %2;" : "=r"(lo), "=r"(hi) : "l"(acc[n][j]));
            o[2*j]   = __uint_as_float(lo);
            o[2*j+1] = __uint_as_float(hi);
        }
        #pragma unroll
        for (int j = 0; j < 8; j++) o[j] = fmaxf(o[j] + bias[j], 0.f);
        *(float4*)(out + node * DIM + jg)     = make_float4(o[0], o[1], o[2], o[3]);
        *(float4*)(out + node * DIM + jg + 4) = make_float4(o[4], o[5], o[6], o[7]);
    }
}

// ---------------------------------------------------------------------------
extern "C" void kernel_launch(void* const* d_in, const int* in_sizes, int n_in,
                              void* d_out, int out_size) {
    const float*     x  = (const float*)d_in[0];
    const long long* ei = (const long long*)d_in[1];
    const float*     W  = (const float*)d_in[2];
    const float*     b  = (const float*)d_in[3];
    float*           out = (float*)d_out;

    k_count<<<(N_EDGES / 2 + 255) / 256, 256>>>(ei);
    k_scan<<<SCAN_BLK, 1024>>>();
    k_fill<<<(N_EDGES + 255) / 256, 256>>>(ei);
    k_aggr<<<(N_NODES + 7) / 8, 256>>>((const float4*)x);

    int grid = (N_NODES + NPB - 1) / NPB;   // 782
    cudaFuncSetAttribute(k_out, cudaFuncAttributeMaxDynamicSharedMemorySize, SMEM_OUT);
    k_out<<<grid, 256, SMEM_OUT>>>((const float4*)x, W, b, out);
}